// round 2
// baseline (speedup 1.0000x reference)
#include <cuda_runtime.h>
#include <cstdint>
#include <cstddef>

// Problem dims (fixed by the reference)
#define B_SZ 32
#define T_SZ 2048
#define F_SZ 512
#define H_SZ 512
#define G4H  2048   // 4*H

// ---------------- scratch (static device globals: allocation-free at runtime) ----
__device__ float g_xw[(size_t)T_SZ * B_SZ * G4H];  // x@Wi + b, laid out [t][b][4H]  (512 MB)
__device__ float g_h[2 * B_SZ * H_SZ];             // double-buffered hidden state
__device__ unsigned g_arrive[4];
__device__ unsigned g_gen[4];

__global__ void reset_kernel() {
    if (threadIdx.x < 4) { g_arrive[threadIdx.x] = 0u; g_gen[threadIdx.x] = 0u; }
}

// ---------------- Pre-GEMM: g_xw[t*B+b][n] = sum_k x[b][t][k]*Wi[k][n] + bias[n] ----
// M = B*T = 65536 (row m = b*T + t), N = 2048, K = 512.
// 128x128 tile, BK=8, 256 threads, 8x8 register tile.
__global__ void __launch_bounds__(256) pregemm_kernel(
    const float* __restrict__ x, const float* __restrict__ Wi,
    const float* __restrict__ bias)
{
    __shared__ float As[8][128];
    __shared__ float Bs[8][128];

    const int tid = threadIdx.x;
    const int m0 = blockIdx.y * 128;
    const int n0 = blockIdx.x * 128;
    const int tx = tid & 15;        // 0..15 -> n micro
    const int ty = tid >> 4;        // 0..15 -> m micro

    const int ar  = tid >> 1;          // 0..127
    const int ac4 = (tid & 1) * 4;     // 0 or 4
    const int br  = tid >> 5;          // 0..7
    const int bc4 = (tid & 31) * 4;    // 0..124

    float acc[8][8];
#pragma unroll
    for (int i = 0; i < 8; i++)
#pragma unroll
        for (int j = 0; j < 8; j++) acc[i][j] = 0.f;

    for (int k0 = 0; k0 < F_SZ; k0 += 8) {
        float4 av = *(const float4*)(x + (size_t)(m0 + ar) * F_SZ + k0 + ac4);
        As[ac4 + 0][ar] = av.x; As[ac4 + 1][ar] = av.y;
        As[ac4 + 2][ar] = av.z; As[ac4 + 3][ar] = av.w;
        *(float4*)&Bs[br][bc4] = *(const float4*)(Wi + (size_t)(k0 + br) * G4H + n0 + bc4);
        __syncthreads();

#pragma unroll
        for (int kk = 0; kk < 8; kk++) {
            float a[8], b[8];
            *(float4*)(a)     = *(const float4*)&As[kk][ty * 8];
            *(float4*)(a + 4) = *(const float4*)&As[kk][ty * 8 + 4];
            *(float4*)(b)     = *(const float4*)&Bs[kk][tx * 8];
            *(float4*)(b + 4) = *(const float4*)&Bs[kk][tx * 8 + 4];
#pragma unroll
            for (int i = 0; i < 8; i++)
#pragma unroll
                for (int j = 0; j < 8; j++)
                    acc[i][j] = fmaf(a[i], b[j], acc[i][j]);
        }
        __syncthreads();
    }

    // epilogue: remap row m=(b*T+t) -> xw row (t*B+b), add bias
#pragma unroll
    for (int i = 0; i < 8; i++) {
        const int m    = m0 + ty * 8 + i;
        const int bidx = m >> 11;       // / T
        const int tdx  = m & (T_SZ - 1);
        float* op = g_xw + ((size_t)tdx * B_SZ + bidx) * G4H + n0 + tx * 8;
        const float* bp = bias + n0 + tx * 8;
        float4 v0 = make_float4(acc[i][0] + bp[0], acc[i][1] + bp[1],
                                acc[i][2] + bp[2], acc[i][3] + bp[3]);
        float4 v1 = make_float4(acc[i][4] + bp[4], acc[i][5] + bp[5],
                                acc[i][6] + bp[6], acc[i][7] + bp[7]);
        *(float4*)(op)     = v0;
        *(float4*)(op + 4) = v1;
    }
}

// ---------------- Recurrence: persistent, 4 groups x 32 CTAs ----------------
// Group g handles batches [8g, 8g+8). CTA r in group owns h-cols [16r, 16r+16)
// => 64 z-columns (4 gates x 16). Wh slice lives in smem for the whole run.

#define WS_STRIDE 516                       // 512 + 4 pad: conflict-free LDS.128
#define SMEM_FLOATS (64 * WS_STRIDE + 8 * WS_STRIDE + 512 + 128)
#define SMEM_BYTES  (SMEM_FLOATS * 4)       // 151,168 bytes

__device__ __forceinline__ void group_barrier(int grp, unsigned n) {
    __syncthreads();
    if (threadIdx.x == 0) {
        __threadfence();
        unsigned a = atomicAdd(&g_arrive[grp], 1u);
        if (a == 31u) {
            atomicExch(&g_arrive[grp], 0u);
            __threadfence();
            atomicAdd(&g_gen[grp], 1u);
        } else {
            while (((volatile unsigned*)g_gen)[grp] < n + 1u) __nanosleep(32);
        }
        __threadfence();
    }
    __syncthreads();
}

__global__ void __launch_bounds__(256) lstm_rec_kernel(
    const float* __restrict__ c0, const float* __restrict__ h0,
    const float* __restrict__ Wh,
    float* __restrict__ outC, float* __restrict__ outH, float* __restrict__ outY)
{
    extern __shared__ float smf[];
    float* ws  = smf;                        // [64][WS_STRIDE]
    float* h_s = smf + 64 * WS_STRIDE;       // [8][WS_STRIDE]
    float* z_s = h_s + 8 * WS_STRIDE;        // [8][64]
    float* c_s = z_s + 512;                  // [128]

    const int tid = threadIdx.x;
    const int grp = blockIdx.x >> 5;
    const int r   = blockIdx.x & 31;
    const int b0  = grp * 8;

    // Load the Wh slice: local col lc = q*16 + jj -> global col q*512 + 16r + jj.
    for (int idx = tid; idx < 64 * 512; idx += 256) {
        int k  = idx >> 6;
        int lc = idx & 63;
        int col = ((lc >> 4) << 9) + (r << 4) + (lc & 15);
        ws[lc * WS_STRIDE + k] = Wh[(size_t)k * G4H + col];
    }
    // Init c (block-local) and h buffer 0 (owned slice only)
    if (tid < 128) {
        int bb = tid >> 4, jj = tid & 15;
        int b = b0 + bb, j = (r << 4) + jj;
        c_s[tid] = c0[b * H_SZ + j];
        g_h[b * H_SZ + j] = h0[b * H_SZ + j];
    }
    unsigned bar_n = 0;
    group_barrier(grp, bar_n++);   // h buffer 0 fully populated within group

    const int lc  = tid & 63;
    const int bbh = tid >> 6;       // 0..3
    const int bbA = bbh * 2, bbB = bbA + 1;
    const int col = ((lc >> 4) << 9) + (r << 4) + (lc & 15);
    const float4* wp = (const float4*)(ws + lc * WS_STRIDE);

    for (int t = 0; t < T_SZ; t++) {
        const int buf = t & 1;

        // Stage h for this group's 8 batches into smem (L2-scoped loads).
        const float* hg = g_h + buf * (B_SZ * H_SZ) + b0 * H_SZ;
        for (int idx = tid; idx < 1024; idx += 256) {
            int bb = idx >> 7, q = idx & 127;
            float4 v = __ldcg((const float4*)(hg + bb * H_SZ) + q);
            *(float4*)(h_s + bb * WS_STRIDE + q * 4) = v;
        }
        __syncthreads();

        const float4* hA = (const float4*)(h_s + bbA * WS_STRIDE);
        const float4* hB = (const float4*)(h_s + bbB * WS_STRIDE);
        const size_t xrow = (size_t)t * B_SZ + b0;
        float xwA = __ldg(&g_xw[(xrow + bbA) * G4H + col]);
        float xwB = __ldg(&g_xw[(xrow + bbB) * G4H + col]);

        float a0 = 0.f, a1 = 0.f, a2 = 0.f, a3 = 0.f;
        float s0 = 0.f, s1 = 0.f, s2 = 0.f, s3 = 0.f;
#pragma unroll 8
        for (int i = 0; i < 128; i++) {
            float4 w  = wp[i];
            float4 ha = hA[i];
            float4 hb = hB[i];
            a0 = fmaf(w.x, ha.x, a0); a1 = fmaf(w.y, ha.y, a1);
            a2 = fmaf(w.z, ha.z, a2); a3 = fmaf(w.w, ha.w, a3);
            s0 = fmaf(w.x, hb.x, s0); s1 = fmaf(w.y, hb.y, s1);
            s2 = fmaf(w.z, hb.z, s2); s3 = fmaf(w.w, hb.w, s3);
        }
        z_s[bbA * 64 + lc] = (a0 + a1) + (a2 + a3) + xwA;
        z_s[bbB * 64 + lc] = (s0 + s1) + (s2 + s3) + xwB;
        __syncthreads();

        if (tid < 128) {
            int bb = tid >> 4, jj = tid & 15;
            float zi = z_s[bb * 64 + jj];
            float zf = z_s[bb * 64 + 16 + jj];
            float zg = z_s[bb * 64 + 32 + jj];
            float zo = z_s[bb * 64 + 48 + jj];
            float ig = 1.f / (1.f + __expf(-zi));
            float fg = 1.f / (1.f + __expf(-zf));
            float gg = tanhf(zg);
            float og = 1.f / (1.f + __expf(-zo));
            float c  = c_s[tid];
            float cn = fmaf(fg, c, ig * gg);
            c_s[tid] = cn;
            float hn = og * tanhf(cn);
            int b = b0 + bb, j = (r << 4) + jj;
            g_h[(buf ^ 1) * (B_SZ * H_SZ) + b * H_SZ + j] = hn;
            outY[((size_t)b * T_SZ + t) * H_SZ + j] = hn;
            if (t == T_SZ - 1) {
                if (outC) outC[b * H_SZ + j] = cn;
                if (outH) outH[b * H_SZ + j] = hn;
            }
        }
        group_barrier(grp, bar_n++);
    }
}

// ---------------- launch ----------------
extern "C" void kernel_launch(void* const* d_in, const int* in_sizes, int n_in,
                              void* d_out, int out_size)
{
    const float* x    = (const float*)d_in[0];
    const float* c0   = (const float*)d_in[1];
    const float* h0   = (const float*)d_in[2];
    const float* Wi   = (const float*)d_in[3];
    const float* Wh   = (const float*)d_in[4];
    const float* bias = (const float*)d_in[5];

    float* out  = (float*)d_out;
    float* outC = nullptr;
    float* outH = nullptr;
    float* outY = out;
    const long long full = 2LL * B_SZ * H_SZ + (long long)B_SZ * T_SZ * H_SZ;
    if ((long long)out_size == full) {
        outC = out;
        outH = out + B_SZ * H_SZ;
        outY = out + 2 * B_SZ * H_SZ;
    }

    cudaFuncSetAttribute(lstm_rec_kernel,
                         cudaFuncAttributeMaxDynamicSharedMemorySize, SMEM_BYTES);

    reset_kernel<<<1, 32>>>();
    pregemm_kernel<<<dim3(G4H / 128, (B_SZ * T_SZ) / 128), 256>>>(x, Wi, bias);
    lstm_rec_kernel<<<128, 256, SMEM_BYTES>>>(c0, h0, Wh, outC, outH, outY);
}

// round 6
// speedup vs baseline: 1.0202x; 1.0202x over previous
#include <cuda_runtime.h>
#include <cstdint>
#include <cstddef>

// Problem dims (fixed by the reference)
#define B_SZ 32
#define T_SZ 2048
#define F_SZ 512
#define H_SZ 512
#define G4H  2048   // 4*H

// ---------------- packed fp32x2 helpers (sm_103a FFMA2) ----------------
__device__ __forceinline__ unsigned long long pack2(float lo, float hi) {
    unsigned long long r;
    asm("mov.b64 %0, {%1, %2};" : "=l"(r) : "f"(lo), "f"(hi));
    return r;
}
__device__ __forceinline__ void ffma2(unsigned long long& d,
                                      unsigned long long a, unsigned long long b) {
    asm("fma.rn.f32x2 %0, %1, %2, %3;" : "=l"(d) : "l"(a), "l"(b), "l"(d));
}
__device__ __forceinline__ unsigned long long add2(unsigned long long a,
                                                   unsigned long long b) {
    unsigned long long r;
    asm("add.rn.f32x2 %0, %1, %2;" : "=l"(r) : "l"(a), "l"(b));
    return r;
}
__device__ __forceinline__ float sum2(unsigned long long p) {
    float lo, hi;
    asm("mov.b64 {%0, %1}, %2;" : "=f"(lo), "=f"(hi) : "l"(p));
    return lo + hi;
}

// ---------------- scratch ----------------
__device__ float g_xw[(size_t)T_SZ * B_SZ * G4H];  // x@Wi + b, [t][b][4H]
__device__ float g_h[2 * B_SZ * H_SZ];             // double-buffered hidden state
__device__ unsigned g_arrive[4];
__device__ unsigned g_gen[4];

__global__ void reset_kernel() {
    if (threadIdx.x < 4) { g_arrive[threadIdx.x] = 0u; g_gen[threadIdx.x] = 0u; }
}

// ---------------- Pre-GEMM with FFMA2 ----------------
// g_xw[t*B+b][n] = sum_k x[b][t][k]*Wi[k][n] + bias[n]
// M = B*T = 65536 (row m = b*T+t), N = 2048, K = 512.
// 128x128 tile, BK=8, 256 threads; 8(m) x 4(n-pair) packed register tile.
__global__ void __launch_bounds__(256) pregemm_kernel(
    const float* __restrict__ x, const float* __restrict__ Wi,
    const float* __restrict__ bias)
{
    __shared__ float As[8][128];
    __shared__ float Bs[8][128];

    const int tid = threadIdx.x;
    const int m0 = blockIdx.y * 128;
    const int n0 = blockIdx.x * 128;
    const int tx = tid & 15;        // n micro (8 floats = 4 pairs)
    const int ty = tid >> 4;        // m micro

    const int ar  = tid >> 1;
    const int ac4 = (tid & 1) * 4;
    const int br  = tid >> 5;
    const int bc4 = (tid & 31) * 4;

    unsigned long long acc2[8][4];
#pragma unroll
    for (int i = 0; i < 8; i++)
#pragma unroll
        for (int j = 0; j < 4; j++) acc2[i][j] = 0ull;

    for (int k0 = 0; k0 < F_SZ; k0 += 8) {
        float4 av = *(const float4*)(x + (size_t)(m0 + ar) * F_SZ + k0 + ac4);
        As[ac4 + 0][ar] = av.x; As[ac4 + 1][ar] = av.y;
        As[ac4 + 2][ar] = av.z; As[ac4 + 3][ar] = av.w;
        *(float4*)&Bs[br][bc4] = *(const float4*)(Wi + (size_t)(k0 + br) * G4H + n0 + bc4);
        __syncthreads();

#pragma unroll
        for (int kk = 0; kk < 8; kk++) {
            float a[8];
            *(float4*)(a)     = *(const float4*)&As[kk][ty * 8];
            *(float4*)(a + 4) = *(const float4*)&As[kk][ty * 8 + 4];
            const ulonglong2* bp = (const ulonglong2*)&Bs[kk][tx * 8];
            ulonglong2 b01 = bp[0];
            ulonglong2 b23 = bp[1];
#pragma unroll
            for (int i = 0; i < 8; i++) {
                unsigned long long a2 = pack2(a[i], a[i]);
                ffma2(acc2[i][0], a2, b01.x);
                ffma2(acc2[i][1], a2, b01.y);
                ffma2(acc2[i][2], a2, b23.x);
                ffma2(acc2[i][3], a2, b23.y);
            }
        }
        __syncthreads();
    }

    // epilogue: remap row m=(b*T+t) -> xw row (t*B+b), add bias
    const float* bp = bias + n0 + tx * 8;
    float bb[8];
    *(float4*)(bb)     = *(const float4*)(bp);
    *(float4*)(bb + 4) = *(const float4*)(bp + 4);
#pragma unroll
    for (int i = 0; i < 8; i++) {
        const int m    = m0 + ty * 8 + i;
        const int bidx = m >> 11;       // / T
        const int tdx  = m & (T_SZ - 1);
        float* op = g_xw + ((size_t)tdx * B_SZ + bidx) * G4H + n0 + tx * 8;
        float o[8];
        union { unsigned long long u; float2 f; } cv;
#pragma unroll
        for (int j = 0; j < 4; j++) {
            cv.u = acc2[i][j];
            o[2 * j]     = cv.f.x + bb[2 * j];
            o[2 * j + 1] = cv.f.y + bb[2 * j + 1];
        }
        *(float4*)(op)     = *(const float4*)(o);
        *(float4*)(op + 4) = *(const float4*)(o + 4);
    }
}

// ---------------- Recurrence: persistent, 4 groups x 32 CTAs ----------------
// Group g: batches [8g, 8g+8). CTA r in group owns 64 z-columns
// (gate q, h-col r*16+jj). Wh slice lives in REGISTERS (64 f32x2/thread).
// Thread (tid): col lc = tid>>2 (0..63), k-chunk kc = tid&3 (128 k each).

#define HS_CHUNK 132                       // 128 + 4 pad (bank spread)
#define HS_BB    (4 * HS_CHUNK)            // 528 floats per batch row

__device__ __forceinline__ void group_barrier(int grp, unsigned n) {
    __syncthreads();
    if (threadIdx.x == 0) {
        __threadfence();
        unsigned a = atomicAdd(&g_arrive[grp], 1u);
        if (a == 31u) {
            atomicExch(&g_arrive[grp], 0u);
            __threadfence();
            atomicAdd(&g_gen[grp], 1u);
        } else {
            while (((volatile unsigned*)g_gen)[grp] < n + 1u) __nanosleep(32);
        }
        __threadfence();
    }
    __syncthreads();
}

__global__ void __launch_bounds__(256) lstm_rec_kernel(
    const float* __restrict__ c0, const float* __restrict__ h0,
    const float* __restrict__ Wh,
    float* __restrict__ outC, float* __restrict__ outH, float* __restrict__ outY)
{
    __shared__ float h_s[8 * HS_BB];   // staged h, padded per k-chunk
    __shared__ float z_s[8 * 64];      // hw partials
    __shared__ float c_s[128];         // cell state (8 batches x 16 cols)

    const int tid = threadIdx.x;
    const int grp = blockIdx.x >> 5;
    const int r   = blockIdx.x & 31;
    const int b0  = grp * 8;

    const int lc  = tid >> 2;                         // 0..63 local column
    const int kc  = tid & 3;                          // k chunk
    const int gcol = ((lc >> 4) << 9) + (r << 4) + (lc & 15);

    // ---- Load this thread's Wh slice into registers (packed k-pairs) ----
    unsigned long long w2[64];
#pragma unroll
    for (int j = 0; j < 64; j++) {
        float lo = Wh[(size_t)(kc * 128 + 2 * j)     * G4H + gcol];
        float hi = Wh[(size_t)(kc * 128 + 2 * j + 1) * G4H + gcol];
        w2[j] = pack2(lo, hi);
    }

    // Init c (block-local) and h buffer 0 (owned slice only)
    if (tid < 128) {
        int bb = tid >> 4, jj = tid & 15;
        int b = b0 + bb, j = (r << 4) + jj;
        c_s[tid] = c0[b * H_SZ + j];
        g_h[b * H_SZ + j] = h0[b * H_SZ + j];
    }
    unsigned bar_n = 0;
    group_barrier(grp, bar_n++);   // h buffer 0 fully populated within group

    for (int t = 0; t < T_SZ; t++) {
        const int buf = t & 1;

        // Stage h for this group's 8 batches into padded smem.
        const float* hg = g_h + buf * (B_SZ * H_SZ) + b0 * H_SZ;
#pragma unroll
        for (int it = 0; it < 4; it++) {
            int idx = tid + it * 256;              // 0..1023 float4 slots
            int bb = idx >> 7, q = idx & 127;      // q: float4 index in [0,128)
            float4 v = __ldcg((const float4*)(hg + bb * H_SZ) + q);
            *(float4*)(h_s + bb * HS_BB + (q >> 5) * HS_CHUNK + (q & 31) * 4) = v;
        }

        // Prefetch xw for the activation phase (depends only on t).
        float xw0 = 0.f, xw1 = 0.f, xw2 = 0.f, xw3 = 0.f;
        if (tid < 128) {
            int bb = tid >> 4, jj = tid & 15;
            const float* xp = g_xw + ((size_t)t * B_SZ + b0 + bb) * G4H + (r << 4) + jj;
            xw0 = __ldg(xp);
            xw1 = __ldg(xp + 512);
            xw2 = __ldg(xp + 1024);
            xw3 = __ldg(xp + 1536);
        }
        __syncthreads();

        // ---- h @ Wh partials: per batch, 64 FFMA2 against register Wh ----
#pragma unroll 1
        for (int bbt = 0; bbt < 8; bbt++) {
            const ulonglong2* hp =
                (const ulonglong2*)(h_s + bbt * HS_BB + kc * HS_CHUNK);
            unsigned long long a0 = 0ull, a1 = 0ull, a2 = 0ull, a3 = 0ull;
#pragma unroll
            for (int i = 0; i < 32; i += 2) {
                ulonglong2 hA = hp[i];
                ulonglong2 hB = hp[i + 1];
                ffma2(a0, w2[2 * i],     hA.x);
                ffma2(a1, w2[2 * i + 1], hA.y);
                ffma2(a2, w2[2 * i + 2], hB.x);
                ffma2(a3, w2[2 * i + 3], hB.y);
            }
            float s = sum2(add2(add2(a0, a1), add2(a2, a3)));
            // reduce the 4 k-chunks (lanes 4c..4c+3 of the same warp)
            s += __shfl_xor_sync(0xFFFFFFFFu, s, 1);
            s += __shfl_xor_sync(0xFFFFFFFFu, s, 2);
            if (kc == 0) z_s[bbt * 64 + lc] = s;
        }
        __syncthreads();

        // ---- gates + state update (128 threads: 8 batches x 16 h-cols) ----
        if (tid < 128) {
            int bb = tid >> 4, jj = tid & 15;
            float zi = z_s[bb * 64 + jj]      + xw0;
            float zf = z_s[bb * 64 + 16 + jj] + xw1;
            float zg = z_s[bb * 64 + 32 + jj] + xw2;
            float zo = z_s[bb * 64 + 48 + jj] + xw3;
            float ig = 1.f / (1.f + __expf(-zi));
            float fg = 1.f / (1.f + __expf(-zf));
            float gg = tanhf(zg);
            float og = 1.f / (1.f + __expf(-zo));
            float c  = c_s[tid];
            float cn = fmaf(fg, c, ig * gg);
            c_s[tid] = cn;
            float hn = og * tanhf(cn);
            int b = b0 + bb, j = (r << 4) + jj;
            g_h[(buf ^ 1) * (B_SZ * H_SZ) + b * H_SZ + j] = hn;
            outY[((size_t)b * T_SZ + t) * H_SZ + j] = hn;
            if (t == T_SZ - 1) {
                if (outC) outC[b * H_SZ + j] = cn;
                if (outH) outH[b * H_SZ + j] = hn;
            }
        }
        group_barrier(grp, bar_n++);
    }
}

// ---------------- launch ----------------
extern "C" void kernel_launch(void* const* d_in, const int* in_sizes, int n_in,
                              void* d_out, int out_size)
{
    const float* x    = (const float*)d_in[0];
    const float* c0   = (const float*)d_in[1];
    const float* h0   = (const float*)d_in[2];
    const float* Wi   = (const float*)d_in[3];
    const float* Wh   = (const float*)d_in[4];
    const float* bias = (const float*)d_in[5];

    float* out  = (float*)d_out;
    float* outC = nullptr;
    float* outH = nullptr;
    float* outY = out;
    const long long full = 2LL * B_SZ * H_SZ + (long long)B_SZ * T_SZ * H_SZ;
    if ((long long)out_size == full) {
        outC = out;
        outH = out + B_SZ * H_SZ;
        outY = out + 2 * B_SZ * H_SZ;
    }

    reset_kernel<<<1, 32>>>();
    pregemm_kernel<<<dim3(G4H / 128, (B_SZ * T_SZ) / 128), 256>>>(x, Wi, bias);
    lstm_rec_kernel<<<128, 256>>>(c0, h0, Wh, outC, outH, outY);
}